// round 4
// baseline (speedup 1.0000x reference)
#include <cuda_runtime.h>

#define BLOCK   128
#define WPB     4
#define NBLOCKS 608
#define NWARPS  (NBLOCKS * WPB)    // 2432 warps
#define NCH     (2 * NWARPS)       // 4864 chunks, 2 per warp
#define WARM    10
#define PSP     36                 // ps row stride (floats)

typedef unsigned long long u64;

__device__ __forceinline__ u64 pk2(float a, float b) {
    u64 r; asm("mov.b64 %0, {%1,%2};" : "=l"(r) : "f"(a), "f"(b)); return r;
}
__device__ __forceinline__ void unpk2(float& a, float& b, u64 r) {
    asm("mov.b64 {%0,%1}, %2;" : "=f"(a), "=f"(b) : "l"(r));
}
__device__ __forceinline__ u64 fma2(u64 a, u64 b, u64 c) {
    u64 d; asm("fma.rn.f32x2 %0, %1, %2, %3;" : "=l"(d) : "l"(a), "l"(b), "l"(c)); return d;
}
__device__ __forceinline__ float fex2(float x) {
    float r; asm("ex2.approx.f32 %0, %1;" : "=f"(r) : "f"(x)); return r;
}
__device__ __forceinline__ float frcp(float x) {
    float r; asm("rcp.approx.f32 %0, %1;" : "=f"(r) : "f"(x)); return r;
}
__device__ __forceinline__ void cpa16(unsigned d, const void* s) {
    asm volatile("cp.async.ca.shared.global [%0], [%1], 16;" :: "r"(d), "l"(s));
}
__device__ __forceinline__ void cpacommit() { asm volatile("cp.async.commit_group;"); }
__device__ __forceinline__ void cpawait0()  { asm volatile("cp.async.wait_group 0;"); }

__global__ void __launch_bounds__(BLOCK, 4) rnn_scan_kernel(
    const float* __restrict__ x, const float* __restrict__ weight,
    const float* __restrict__ weight_y, const float* __restrict__ bias,
    const float* __restrict__ weight_ln, const float* __restrict__ bias_ln,
    float* __restrict__ out, int B, int L)
{
    __shared__ __align__(16) float xs[WPB][2][2][16][16];  // [warp][stage][chunk][row][16]
    __shared__ __align__(16) float ps[WPB][32][PSP];       // rows 0-15: A, 16-31: B

    const int w    = threadIdx.x >> 5;
    const int lane = threadIdx.x & 31;
    const int wid  = blockIdx.x * WPB + w;

    const int startA = (2 * wid) * L;
    const int startB = (2 * wid + 1) * L;
    if (startA >= B) return;
    const bool actB = (startB < B);

    const int t0A    = max(0, startA - WARM);
    const int t0B    = actB ? max(0, startB - WARM) : 0;
    const int sstopA = min(startA + L, B);
    const int sstopB = actB ? min(startB + L, B) : 0;
    const int ntA    = (sstopA - t0A + 15) >> 4;
    const int ntB    = actB ? ((sstopB - t0B + 15) >> 4) : 0;
    const int nt     = max(ntA, ntB);
    const int tstopA = sstopA;
    const int tstopB = actB ? sstopB : 0x40000000;  // inactive: always full tiles (garbage, never stored)

    const float SC = -1.4426950408889634f;  // -log2(e) folded into all y-weights

    // Lane owns hidden (h0,h1)=(2l,2l+1); crossed-half chains so the x multiplier
    // is the natural pair {x_2k, x_2k+1}: z[h0]=c0.lo+c1.hi, z[h1]=c1.lo+c0.hi.
    const int h0 = 2 * lane, h1 = 2 * lane + 1;
    u64 w0k[8], w1k[8];
#pragma unroll
    for (int k = 0; k < 8; k++) {
        const float* r0 = weight + (2 * k) * 64;
        const float* r1 = weight + (2 * k + 1) * 64;
        w0k[k] = pk2(SC * r0[h0], SC * r1[h1]);
        w1k[k] = pk2(SC * r0[h1], SC * r1[h0]);
    }
    const float wyz0 = SC * weight_y[h0];
    const float wyz1 = SC * weight_y[h1];
    const float wl0  = weight_ln[h0];
    const float wl1  = weight_ln[h1];
    const float bln  = bias_ln[0];
    const u64 binit  = pk2(SC * bias[0], 0.f);

    // Two independent recurrence chains (double ILP on the serial sigmoid path)
    float zA0 = 0.f, zA1 = 0.f, sA0 = 0.f, sA1 = 0.f;
    float zB0 = 0.f, zB1 = 0.f, sB0 = 0.f, sB1 = 0.f;

    const int jr = lane >> 3;      // 0..3: row sub-block
    const int q  = lane & 7;       // 0..7 -> but x row is 16 floats = 4 quarters...
    // Remap: 16 rows x 4 quarters = 64 lane-slots; use 2 rows per lane group of 8:
    const int rr = lane >> 2;      // 0..7
    const int qq = lane & 3;       // 0..3

    auto issue = [&](int tbA_, int tbB_, int st) {
        // chunk tile = 16 rows x 64B; lane covers rows rr, rr+8 quarter qq (16B each)
#pragma unroll
        for (int r = 0; r < 2; r++) {
            int rowid = r * 8 + rr;
            int tA = min(tbA_ + rowid, B - 1);
            cpa16((unsigned)__cvta_generic_to_shared(&xs[w][st][0][rowid][qq * 4]),
                  x + (size_t)tA * 64 + qq * 4);
            int tB = min(tbB_ + rowid, B - 1);
            cpa16((unsigned)__cvta_generic_to_shared(&xs[w][st][1][rowid][qq * 4]),
                  x + (size_t)tB * 64 + qq * 4);
        }
    };

    auto step = [&](const float* xrow, float& z0, float& z1, float& s0, float& s1, int psrow) {
        ulonglong2 qa = *(const ulonglong2*)(xrow);
        ulonglong2 qb = *(const ulonglong2*)(xrow + 4);
        ulonglong2 qc = *(const ulonglong2*)(xrow + 8);
        ulonglong2 qd = *(const ulonglong2*)(xrow + 12);
        u64 c0 = binit, c1 = binit;
        c0 = fma2(qa.x, w0k[0], c0);  c1 = fma2(qa.x, w1k[0], c1);
        c0 = fma2(qa.y, w0k[1], c0);  c1 = fma2(qa.y, w1k[1], c1);
        c0 = fma2(qb.x, w0k[2], c0);  c1 = fma2(qb.x, w1k[2], c1);
        c0 = fma2(qb.y, w0k[3], c0);  c1 = fma2(qb.y, w1k[3], c1);
        c0 = fma2(qc.x, w0k[4], c0);  c1 = fma2(qc.x, w1k[4], c1);
        c0 = fma2(qc.y, w0k[5], c0);  c1 = fma2(qc.y, w1k[5], c1);
        c0 = fma2(qd.x, w0k[6], c0);  c1 = fma2(qd.x, w1k[6], c1);
        c0 = fma2(qd.y, w0k[7], c0);  c1 = fma2(qd.y, w1k[7], c1);
        float a0, b0, a1, b1;
        unpk2(a0, b0, c0);
        unpk2(a1, b1, c1);
        z0 = fmaf(wyz0, s0, a0 + b1);          // bias folded once via binit.lo
        z1 = fmaf(wyz1, s1, a1 + b0);
        s0 = frcp(1.f + fex2(z0));             // sigma(y) = 1/(1+2^z), z = -y*log2e
        s1 = frcp(1.f + fex2(z1));
        ps[w][psrow][lane] = fmaf(s1, wl1, s0 * wl0);
    };

    int tbA = t0A, tbB = t0B;

    auto reduceStore = [&]() {
        const int  l16 = lane & 15;
        const bool isA = (lane < 16);
        const int  t   = (isA ? tbA : tbB) + l16;
        const int  st_ = isA ? startA : startB;
        const int  sp_ = isA ? sstopA : sstopB;
        if (t >= st_ && t < sp_) {
            const float4* pr = (const float4*)(&ps[w][lane][0]);
            float4 a0 = pr[0], a1 = pr[1], a2 = pr[2], a3 = pr[3];
            float4 a4 = pr[4], a5 = pr[5], a6 = pr[6], a7 = pr[7];
            float r0 = ((a0.x + a0.y) + (a0.z + a0.w)) + ((a1.x + a1.y) + (a1.z + a1.w));
            float r1 = ((a2.x + a2.y) + (a2.z + a2.w)) + ((a3.x + a3.y) + (a3.z + a3.w));
            float r2 = ((a4.x + a4.y) + (a4.z + a4.w)) + ((a5.x + a5.y) + (a5.z + a5.w));
            float r3 = ((a6.x + a6.y) + (a6.z + a6.w)) + ((a7.x + a7.y) + (a7.z + a7.w));
            out[t] = bln + ((r0 + r1) + (r2 + r3));
        }
    };

    // Prologue: load tile 0 for both chunks
    issue(tbA, tbB, 0);
    cpacommit();
    cpawait0();
    __syncwarp();

    for (int k = 0; k < nt; k++) {
        const int st = k & 1;
        if (k + 1 < nt) { issue(tbA + 16, tbB + 16, st ^ 1); cpacommit(); }

        const int nA = max(0, min(16, tstopA - tbA));
        const int nB = max(0, min(16, tstopB - tbB));
        const float (*xa)[16] = xs[w][st][0];
        const float (*xb)[16] = xs[w][st][1];

        if (nA == 16 && nB == 16) {
#pragma unroll
            for (int j = 0; j < 16; j++) {
                step(xa[j], zA0, zA1, sA0, sA1, j);       // chains interleave across A/B
                step(xb[j], zB0, zB1, sB0, sB1, 16 + j);
            }
        } else {
            for (int j = 0; j < 16; j++) {
                if (j < nA) step(xa[j], zA0, zA1, sA0, sA1, j);
                if (j < nB) step(xb[j], zB0, zB1, sB0, sB1, 16 + j);
            }
        }
        __syncwarp();
        reduceStore();   // lanes 0-15: A steps tbA+0..15 ; lanes 16-31: B steps
        __syncwarp();

        if (k + 1 < nt) { cpawait0(); __syncwarp(); }
        tbA += 16; tbB += 16;
    }

    // Final-carry chunk (exactly one globally): y = z * (-ln2) undoes the fold
    const float NL2 = -0.6931471805599453f;
    if (startA + L >= B) {
        *(float2*)(out + B + 2 * lane)      = make_float2(zA0 * NL2, zA1 * NL2);
        *(float2*)(out + B + 64 + 2 * lane) = make_float2(sA0, sA1);
    }
    if (actB && startB + L >= B) {
        *(float2*)(out + B + 2 * lane)      = make_float2(zB0 * NL2, zB1 * NL2);
        *(float2*)(out + B + 64 + 2 * lane) = make_float2(sB0, sB1);
    }
}

extern "C" void kernel_launch(void* const* d_in, const int* in_sizes, int n_in,
                              void* d_out, int out_size)
{
    const float* x   = (const float*)d_in[0];
    const float* wt  = (const float*)d_in[1];
    const float* wy  = (const float*)d_in[2];
    const float* b   = (const float*)d_in[3];
    const float* wln = (const float*)d_in[4];
    const float* bln = (const float*)d_in[5];
    float* out = (float*)d_out;

    const int B = in_sizes[0] / 64;              // x is (B, T=4, I=16); row stride 64
    const int L = (B + NCH - 1) / NCH;           // steps per chunk (2 chunks per warp)

    rnn_scan_kernel<<<NBLOCKS, BLOCK>>>(x, wt, wy, b, wln, bln, out, B, L);
}

// round 5
// speedup vs baseline: 1.0052x; 1.0052x over previous
#include <cuda_runtime.h>

#define BLOCK   128
#define WPB     4
#define NSM     152
#define OCC     7
#define NBLOCKS (NSM * OCC)          // 1064
#define NWARPS  (NBLOCKS * WPB)      // 4256 chunks, 1 per warp
#define WARM    12
#define PSP     36

typedef unsigned long long u64;

__device__ __forceinline__ u64 pk2(float a, float b) {
    u64 r; asm("mov.b64 %0, {%1,%2};" : "=l"(r) : "f"(a), "f"(b)); return r;
}
__device__ __forceinline__ void unpk2(float& a, float& b, u64 r) {
    asm("mov.b64 {%0,%1}, %2;" : "=f"(a), "=f"(b) : "l"(r));
}
__device__ __forceinline__ u64 fma2(u64 a, u64 b, u64 c) {
    u64 d; asm("fma.rn.f32x2 %0, %1, %2, %3;" : "=l"(d) : "l"(a), "l"(b), "l"(c)); return d;
}
__device__ __forceinline__ float fex2(float x) {
    float r; asm("ex2.approx.f32 %0, %1;" : "=f"(r) : "f"(x)); return r;
}
__device__ __forceinline__ float frcp(float x) {
    float r; asm("rcp.approx.f32 %0, %1;" : "=f"(r) : "f"(x)); return r;
}
__device__ __forceinline__ void cpa16(unsigned d, const void* s) {
    asm volatile("cp.async.ca.shared.global [%0], [%1], 16;" :: "r"(d), "l"(s));
}
__device__ __forceinline__ void cpacommit() { asm volatile("cp.async.commit_group;"); }
__device__ __forceinline__ void cpawait0()  { asm volatile("cp.async.wait_group 0;"); }

__global__ void __launch_bounds__(BLOCK, OCC) rnn_scan_kernel(
    const float* __restrict__ x, const float* __restrict__ weight,
    const float* __restrict__ weight_y, const float* __restrict__ bias,
    const float* __restrict__ weight_ln, const float* __restrict__ bias_ln,
    float* __restrict__ out, int B, int L)
{
    __shared__ __align__(16) float xs[WPB][2][16][16];   // [warp][stage][row][16]
    __shared__ __align__(16) float ps[WPB][16][PSP];     // per-step per-lane partials

    const int w    = threadIdx.x >> 5;
    const int lane = threadIdx.x & 31;
    const int wid  = blockIdx.x * WPB + w;
    const int start = wid * L;
    if (start >= B) return;
    const int tstop = min(start + L, B);
    const int t0    = max(0, start - WARM);   // contraction warmup (<=0.25^12)
    const int nt    = (tstop - t0 + 15) >> 4;

    const float SC = -1.4426950408889634f;    // -log2(e) folded into y-weights

    // Lane owns hidden (h0,h1)=(2l,2l+1); crossed-half chains so the x multiplier
    // is the natural pair {x_2k,x_2k+1}: z[h0]=c0.lo+c1.hi, z[h1]=c1.lo+c0.hi.
    const int h0 = 2 * lane, h1 = 2 * lane + 1;
    u64 w0k[8], w1k[8];
#pragma unroll
    for (int k = 0; k < 8; k++) {
        const float* r0 = weight + (2 * k) * 64;
        const float* r1 = weight + (2 * k + 1) * 64;
        w0k[k] = pk2(SC * r0[h0], SC * r1[h1]);
        w1k[k] = pk2(SC * r0[h1], SC * r1[h0]);
    }
    const float wyz0 = SC * weight_y[h0];
    const float wyz1 = SC * weight_y[h1];
    const float wl0  = weight_ln[h0];
    const float wl1  = weight_ln[h1];
    const float bln  = bias_ln[0];
    const u64 binit  = pk2(SC * bias[0], 0.f);

    float z0 = 0.f, z1 = 0.f, s0 = 0.f, s1 = 0.f;

    // cp.async mapping: 16 rows x 4 quarters (16B) = 64 slots; lane covers
    // slots {lane, lane+32}.
    auto issue = [&](int tb, int st) {
#pragma unroll
        for (int r = 0; r < 2; r++) {
            int slot = lane + r * 32;
            int row = slot >> 2, q = slot & 3;
            int t = min(tb + row, B - 1);
            cpa16((unsigned)__cvta_generic_to_shared(&xs[w][st][row][q * 4]),
                  x + (size_t)t * 64 + q * 4);
        }
    };

    auto step = [&](const float* xrow, int j) {
        u64 c0 = binit, c1 = binit;
        {   // first half: x[0..7]
            ulonglong2 qa = *(const ulonglong2*)(xrow);
            ulonglong2 qb = *(const ulonglong2*)(xrow + 4);
            c0 = fma2(qa.x, w0k[0], c0);  c1 = fma2(qa.x, w1k[0], c1);
            c0 = fma2(qa.y, w0k[1], c0);  c1 = fma2(qa.y, w1k[1], c1);
            c0 = fma2(qb.x, w0k[2], c0);  c1 = fma2(qb.x, w1k[2], c1);
            c0 = fma2(qb.y, w0k[3], c0);  c1 = fma2(qb.y, w1k[3], c1);
        }
        {   // second half: x[8..15]
            ulonglong2 qc = *(const ulonglong2*)(xrow + 8);
            ulonglong2 qd = *(const ulonglong2*)(xrow + 12);
            c0 = fma2(qc.x, w0k[4], c0);  c1 = fma2(qc.x, w1k[4], c1);
            c0 = fma2(qc.y, w0k[5], c0);  c1 = fma2(qc.y, w1k[5], c1);
            c0 = fma2(qd.x, w0k[6], c0);  c1 = fma2(qd.x, w1k[6], c1);
            c0 = fma2(qd.y, w0k[7], c0);  c1 = fma2(qd.y, w1k[7], c1);
        }
        float a0, b0, a1, b1;
        unpk2(a0, b0, c0);
        unpk2(a1, b1, c1);
        z0 = fmaf(wyz0, s0, a0 + b1);       // bias folded once via binit.lo
        z1 = fmaf(wyz1, s1, a1 + b0);
        s0 = frcp(1.f + fex2(z0));          // sigma(y) = 1/(1+2^z), z=-y*log2e
        s1 = frcp(1.f + fex2(z1));
        ps[w][j][lane] = fmaf(s1, wl1, s0 * wl0);
    };

    // Prologue
    issue(t0, 0);
    cpacommit();
    cpawait0();
    __syncwarp();

    int tb = t0;
    const int jj   = lane & 15;   // step within tile this lane reduces
    const int half = lane >> 4;   // which 16 partials

    for (int k = 0; k < nt; k++) {
        const int st = k & 1;
        if (k + 1 < nt) { issue(tb + 16, st ^ 1); cpacommit(); }

        const int n = min(16, tstop - tb);
        const float (*xa)[16] = xs[w][st];
        if (n == 16) {
#pragma unroll
            for (int j = 0; j < 16; j++) step(xa[j], j);
        } else {
            for (int j = 0; j < n; j++) step(xa[j], j);
        }
        __syncwarp();

        // Reduce: lane (half, jj) sums 16 partials of step tb+jj; shfl-combine halves
        {
            const float4* pr = (const float4*)(&ps[w][jj][half * 16]);
            float4 a0 = pr[0], a1 = pr[1], a2 = pr[2], a3 = pr[3];
            float r0 = ((a0.x + a0.y) + (a0.z + a0.w)) + ((a1.x + a1.y) + (a1.z + a1.w));
            float r1 = ((a2.x + a2.y) + (a2.z + a2.w)) + ((a3.x + a3.y) + (a3.z + a3.w));
            float r = r0 + r1;
            r += __shfl_xor_sync(0xffffffffu, r, 16);
            int t = tb + jj;
            if (half == 0 && t >= start && t < tstop)
                out[t] = bln + r;                    // 16-lane 64B store per tile
        }
        __syncwarp();

        if (k + 1 < nt) { cpawait0(); __syncwarp(); }
        tb += 16;
    }

    // Unique last chunk writes final carries; y = z * (-ln2) undoes the fold
    if (start + L >= B) {
        const float NL2 = -0.6931471805599453f;
        *(float2*)(out + B + 2 * lane)      = make_float2(z0 * NL2, z1 * NL2);  // y_h
        *(float2*)(out + B + 64 + 2 * lane) = make_float2(s0, s1);              // y_hs
    }
}

extern "C" void kernel_launch(void* const* d_in, const int* in_sizes, int n_in,
                              void* d_out, int out_size)
{
    const float* x   = (const float*)d_in[0];
    const float* wt  = (const float*)d_in[1];
    const float* wy  = (const float*)d_in[2];
    const float* b   = (const float*)d_in[3];
    const float* wln = (const float*)d_in[4];
    const float* bln = (const float*)d_in[5];
    float* out = (float*)d_out;

    const int B = in_sizes[0] / 64;              // x is (B, T=4, I=16); row stride 64
    const int L = (B + NWARPS - 1) / NWARPS;     // steps per chunk

    rnn_scan_kernel<<<NBLOCKS, BLOCK>>>(x, wt, wy, b, wln, bln, out, B, L);
}

// round 6
// speedup vs baseline: 1.1405x; 1.1346x over previous
#include <cuda_runtime.h>

#define BLOCK   128
#define WPB     4
#define NSM     152
#define OCC     8
#define NBLOCKS (NSM * OCC)          // 1216
#define NWARPS  (NBLOCKS * WPB)      // 4864 chunks, 1 per warp
#define WARM    12
#define PSP     36

typedef unsigned long long u64;

__device__ __forceinline__ u64 pk2(float a, float b) {
    u64 r; asm("mov.b64 %0, {%1,%2};" : "=l"(r) : "f"(a), "f"(b)); return r;
}
__device__ __forceinline__ void unpk2(float& a, float& b, u64 r) {
    asm("mov.b64 {%0,%1}, %2;" : "=f"(a), "=f"(b) : "l"(r));
}
__device__ __forceinline__ u64 fma2(u64 a, u64 b, u64 c) {
    u64 d; asm("fma.rn.f32x2 %0, %1, %2, %3;" : "=l"(d) : "l"(a), "l"(b), "l"(c)); return d;
}
__device__ __forceinline__ float ftanh(float x) {
    float r; asm("tanh.approx.f32 %0, %1;" : "=f"(r) : "f"(x)); return r;
}
__device__ __forceinline__ void cpa16(unsigned d, const void* s) {
    asm volatile("cp.async.ca.shared.global [%0], [%1], 16;" :: "r"(d), "l"(s));
}
__device__ __forceinline__ void cpacommit() { asm volatile("cp.async.commit_group;"); }
__device__ __forceinline__ void cpawait0()  { asm volatile("cp.async.wait_group 0;"); }

__global__ void __launch_bounds__(BLOCK, OCC) rnn_scan_kernel(
    const float* __restrict__ x, const float* __restrict__ weight,
    const float* __restrict__ weight_y, const float* __restrict__ bias,
    const float* __restrict__ weight_ln, const float* __restrict__ bias_ln,
    float* __restrict__ out, int B, int L)
{
    __shared__ __align__(16) float xs[WPB][2][16][16];   // [warp][stage][row][16]
    __shared__ __align__(16) float ps[WPB][16][PSP];     // per-step per-lane partials

    const int w    = threadIdx.x >> 5;
    const int lane = threadIdx.x & 31;
    const int wid  = blockIdx.x * WPB + w;
    const int start = wid * L;
    if (start >= B) return;
    const int tstop = min(start + L, B);
    const int t0    = max(0, start - WARM);   // contraction warmup (<=0.25^12)
    const int nt    = (tstop - t0 + 15) >> 4;

    // sigma(y) = 0.5 + 0.5*tanh(y/2). Fold 0.5 into W and bias: z = y/2.
    // Recurrence on t = tanh(z):  wy*s = 0.5*wy + 0.5*wy*t, so
    //   z = (0.5*bias + 0.25*wy_h) + x·(0.5 W) + (0.25*wy_h)*t
    const float SC = 0.5f;

    // Lane owns hidden (h0,h1)=(2l,2l+1); crossed-half chains: x multiplier is
    // the natural pair {x_2k,x_2k+1}: z[h0]=c0.lo+c1.hi, z[h1]=c1.lo+c0.hi.
    const int h0 = 2 * lane, h1 = 2 * lane + 1;
    u64 w0k[8], w1k[8];
#pragma unroll
    for (int k = 0; k < 8; k++) {
        const float* r0 = weight + (2 * k) * 64;
        const float* r1 = weight + (2 * k + 1) * 64;
        w0k[k] = pk2(SC * r0[h0], SC * r1[h1]);
        w1k[k] = pk2(SC * r0[h1], SC * r1[h0]);
    }
    const float wyt0 = 0.25f * weight_y[h0];          // multiplier of t
    const float wyt1 = 0.25f * weight_y[h1];
    const float hl0  = 0.5f * weight_ln[h0];
    const float hl1  = 0.5f * weight_ln[h1];
    const float hsum = hl0 + hl1;                      // per-lane constant term
    const float bln  = bias_ln[0];
    const u64 binit0 = pk2(SC * bias[0] + wyt0, 0.f);  // bias' for h0-chain
    const u64 binit1 = pk2(SC * bias[0] + wyt1, 0.f);  // bias' for h1-chain

    float z0 = 0.f, z1 = 0.f;
    float t0s = -1.f, t1s = -1.f;    // t = 2s-1; s_init = 0 -> t = -1

    // cp.async mapping: 16 rows x 4 quarters (16B) = 64 slots; lane covers
    // slots {lane, lane+32}.
    auto issue = [&](int tb, int st) {
#pragma unroll
        for (int r = 0; r < 2; r++) {
            int slot = lane + r * 32;
            int row = slot >> 2, q = slot & 3;
            int t = min(tb + row, B - 1);
            cpa16((unsigned)__cvta_generic_to_shared(&xs[w][st][row][q * 4]),
                  x + (size_t)t * 64 + q * 4);
        }
    };

    auto step = [&](const float* xrow, int j) {
        u64 c0 = binit0, c1 = binit1;
        {   // first half: x[0..7]
            ulonglong2 qa = *(const ulonglong2*)(xrow);
            ulonglong2 qb = *(const ulonglong2*)(xrow + 4);
            c0 = fma2(qa.x, w0k[0], c0);  c1 = fma2(qa.x, w1k[0], c1);
            c0 = fma2(qa.y, w0k[1], c0);  c1 = fma2(qa.y, w1k[1], c1);
            c0 = fma2(qb.x, w0k[2], c0);  c1 = fma2(qb.x, w1k[2], c1);
            c0 = fma2(qb.y, w0k[3], c0);  c1 = fma2(qb.y, w1k[3], c1);
        }
        {   // second half: x[8..15]
            ulonglong2 qc = *(const ulonglong2*)(xrow + 8);
            ulonglong2 qd = *(const ulonglong2*)(xrow + 12);
            c0 = fma2(qc.x, w0k[4], c0);  c1 = fma2(qc.x, w1k[4], c1);
            c0 = fma2(qc.y, w0k[5], c0);  c1 = fma2(qc.y, w1k[5], c1);
            c0 = fma2(qd.x, w0k[6], c0);  c1 = fma2(qd.x, w1k[6], c1);
            c0 = fma2(qd.y, w0k[7], c0);  c1 = fma2(qd.y, w1k[7], c1);
        }
        float a0, b0, a1, b1;
        unpk2(a0, b0, c0);
        unpk2(a1, b1, c1);
        z0 = fmaf(wyt0, t0s, a0 + b1);     // bias' folded once via binit.lo
        z1 = fmaf(wyt1, t1s, a1 + b0);
        t0s = ftanh(z0);                   // single MUFU per scalar
        t1s = ftanh(z1);
        ps[w][j][lane] = fmaf(hl1, t1s, fmaf(hl0, t0s, hsum));
    };

    // Prologue
    issue(t0, 0);
    cpacommit();
    cpawait0();
    __syncwarp();

    int tb = t0;
    const int jj   = lane & 15;   // step within tile this lane reduces
    const int half = lane >> 4;   // which 16 partials

    for (int k = 0; k < nt; k++) {
        const int st = k & 1;
        if (k + 1 < nt) { issue(tb + 16, st ^ 1); cpacommit(); }

        const int n = min(16, tstop - tb);
        const float (*xa)[16] = xs[w][st];
        if (n == 16) {
#pragma unroll
            for (int j = 0; j < 16; j++) step(xa[j], j);
        } else {
            for (int j = 0; j < n; j++) step(xa[j], j);
        }
        __syncwarp();

        // Reduce: lane (half, jj) sums 16 partials of step tb+jj; shfl-combine halves
        {
            const float4* pr = (const float4*)(&ps[w][jj][half * 16]);
            float4 a0 = pr[0], a1 = pr[1], a2 = pr[2], a3 = pr[3];
            float r0 = ((a0.x + a0.y) + (a0.z + a0.w)) + ((a1.x + a1.y) + (a1.z + a1.w));
            float r1 = ((a2.x + a2.y) + (a2.z + a2.w)) + ((a3.x + a3.y) + (a3.z + a3.w));
            float r = r0 + r1;
            r += __shfl_xor_sync(0xffffffffu, r, 16);
            int t = tb + jj;
            if (half == 0 && t >= start && t < tstop)
                out[t] = bln + r;                    // 16-lane 64B store per tile
        }
        __syncwarp();

        if (k + 1 < nt) { cpawait0(); __syncwarp(); }
        tb += 16;
    }

    // Unique last chunk writes final carries: y_h = 2z, y_hs = 0.5 + 0.5*t
    if (start + L >= B) {
        *(float2*)(out + B + 2 * lane) = make_float2(2.f * z0, 2.f * z1);
        *(float2*)(out + B + 64 + 2 * lane) =
            make_float2(fmaf(0.5f, t0s, 0.5f), fmaf(0.5f, t1s, 0.5f));
    }
}

extern "C" void kernel_launch(void* const* d_in, const int* in_sizes, int n_in,
                              void* d_out, int out_size)
{
    const float* x   = (const float*)d_in[0];
    const float* wt  = (const float*)d_in[1];
    const float* wy  = (const float*)d_in[2];
    const float* b   = (const float*)d_in[3];
    const float* wln = (const float*)d_in[4];
    const float* bln = (const float*)d_in[5];
    float* out = (float*)d_out;

    const int B = in_sizes[0] / 64;              // x is (B, T=4, I=16); row stride 64
    const int L = (B + NWARPS - 1) / NWARPS;     // steps per chunk

    rnn_scan_kernel<<<NBLOCKS, BLOCK>>>(x, wt, wy, b, wln, bln, out, B, L);
}

// round 7
// speedup vs baseline: 1.2665x; 1.1105x over previous
#include <cuda_runtime.h>

#define BLOCK   128
#define WPB     4
#define NSM     152
#define OCC     7
#define NBLOCKS (NSM * OCC)          // 1064
#define NWARPS  (NBLOCKS * WPB)      // 4256 chunks, 1 per warp
#define WARM    12
#define PSP     36

typedef unsigned long long u64;

__device__ __forceinline__ u64 pk2(float a, float b) {
    u64 r; asm("mov.b64 %0, {%1,%2};" : "=l"(r) : "f"(a), "f"(b)); return r;
}
__device__ __forceinline__ void unpk2(float& a, float& b, u64 r) {
    asm("mov.b64 {%0,%1}, %2;" : "=f"(a), "=f"(b) : "l"(r));
}
__device__ __forceinline__ u64 fma2(u64 a, u64 b, u64 c) {
    u64 d; asm("fma.rn.f32x2 %0, %1, %2, %3;" : "=l"(d) : "l"(a), "l"(b), "l"(c)); return d;
}
__device__ __forceinline__ float ftanh(float x) {
    float r; asm("tanh.approx.f32 %0, %1;" : "=f"(r) : "f"(x)); return r;
}
__device__ __forceinline__ void cpa16(unsigned d, const void* s) {
    asm volatile("cp.async.ca.shared.global [%0], [%1], 16;" :: "r"(d), "l"(s));
}
__device__ __forceinline__ void cpacommit() { asm volatile("cp.async.commit_group;"); }
__device__ __forceinline__ void cpawait0()  { asm volatile("cp.async.wait_group 0;"); }

__global__ void __launch_bounds__(BLOCK, OCC) rnn_scan_kernel(
    const float* __restrict__ x, const float* __restrict__ weight,
    const float* __restrict__ weight_y, const float* __restrict__ bias,
    const float* __restrict__ weight_ln, const float* __restrict__ bias_ln,
    float* __restrict__ out, int B, int L)
{
    __shared__ __align__(16) float xs[WPB][2][16][16];    // x tiles, double-buffered
    __shared__ __align__(16) float ps[WPB][2][16][PSP];   // partials, double-buffered

    const int w    = threadIdx.x >> 5;
    const int lane = threadIdx.x & 31;
    const int wid  = blockIdx.x * WPB + w;
    const int start = wid * L;
    if (start >= B) return;
    const int tstop = min(start + L, B);
    const int t0    = max(0, start - WARM);   // contraction warmup (<=0.25^12)
    const int nt    = (tstop - t0 + 15) >> 4;

    // sigma(y) = 0.5 + 0.5*tanh(y/2); z = y/2; state t = tanh(z):
    //   z = (0.5*bias + 0.25*wy_h) + x·(0.5 W) + (0.25*wy_h)*t
    const float SC = 0.5f;

    // Lane owns hidden (h0,h1)=(2l,2l+1); crossed-half chains: x multiplier is
    // the natural pair {x_2k,x_2k+1}: z[h0]=c0.lo+c1.hi, z[h1]=c1.lo+c0.hi.
    const int h0 = 2 * lane, h1 = 2 * lane + 1;
    u64 w0k[8], w1k[8];
#pragma unroll
    for (int k = 0; k < 8; k++) {
        const float* r0 = weight + (2 * k) * 64;
        const float* r1 = weight + (2 * k + 1) * 64;
        w0k[k] = pk2(SC * r0[h0], SC * r1[h1]);
        w1k[k] = pk2(SC * r0[h1], SC * r1[h0]);
    }
    const float wyt0 = 0.25f * weight_y[h0];
    const float wyt1 = 0.25f * weight_y[h1];
    const float hl0  = 0.5f * weight_ln[h0];
    const float hl1  = 0.5f * weight_ln[h1];
    const float hsum = hl0 + hl1;
    const float bln  = bias_ln[0];
    const u64 binit0 = pk2(SC * bias[0] + wyt0, 0.f);
    const u64 binit1 = pk2(SC * bias[0] + wyt1, 0.f);

    float z0 = 0.f, z1 = 0.f;
    float t0s = -1.f, t1s = -1.f;    // t = 2s-1; s_init = 0 -> t = -1

    auto issue = [&](int tb, int st) {
#pragma unroll
        for (int r = 0; r < 2; r++) {
            int slot = lane + r * 32;
            int row = slot >> 2, q = slot & 3;
            int t = min(tb + row, B - 1);
            cpa16((unsigned)__cvta_generic_to_shared(&xs[w][st][row][q * 4]),
                  x + (size_t)t * 64 + q * 4);
        }
    };

    // matvec: state-independent part of the step (4 LDS + 16 fma2)
    auto matvec = [&](const float* xrow, float& m0, float& m1) {
        ulonglong2 qa = *(const ulonglong2*)(xrow);
        ulonglong2 qb = *(const ulonglong2*)(xrow + 4);
        ulonglong2 qc = *(const ulonglong2*)(xrow + 8);
        ulonglong2 qd = *(const ulonglong2*)(xrow + 12);
        u64 c0 = binit0, c1 = binit1;
        c0 = fma2(qa.x, w0k[0], c0);  c1 = fma2(qa.x, w1k[0], c1);
        c0 = fma2(qa.y, w0k[1], c0);  c1 = fma2(qa.y, w1k[1], c1);
        c0 = fma2(qb.x, w0k[2], c0);  c1 = fma2(qb.x, w1k[2], c1);
        c0 = fma2(qb.y, w0k[3], c0);  c1 = fma2(qb.y, w1k[3], c1);
        c0 = fma2(qc.x, w0k[4], c0);  c1 = fma2(qc.x, w1k[4], c1);
        c0 = fma2(qc.y, w0k[5], c0);  c1 = fma2(qc.y, w1k[5], c1);
        c0 = fma2(qd.x, w0k[6], c0);  c1 = fma2(qd.x, w1k[6], c1);
        c0 = fma2(qd.y, w0k[7], c0);  c1 = fma2(qd.y, w1k[7], c1);
        float a0, b0, a1, b1;
        unpk2(a0, b0, c0);
        unpk2(a1, b1, c1);
        m0 = a0 + b1;
        m1 = a1 + b0;
    };

    // recur: the only serial part (2 FFMA + 2 TANH + partial)
    auto recur = [&](float m0, float m1, int st, int j) {
        z0 = fmaf(wyt0, t0s, m0);
        z1 = fmaf(wyt1, t1s, m1);
        t0s = ftanh(z0);
        t1s = ftanh(z1);
        ps[w][st][j][lane] = fmaf(hl1, t1s, fmaf(hl0, t0s, hsum));
    };

    // Prologue
    issue(t0, 0);
    cpacommit();
    cpawait0();
    __syncwarp();

    float m0, m1;
    matvec(xs[w][0][0], m0, m1);

    int tb = t0;
    const int jj   = lane & 15;
    const int half = lane >> 4;

    for (int k = 0; k < nt; k++) {
        const int st = k & 1;
        if (k + 1 < nt) { issue(tb + 16, st ^ 1); cpacommit(); }

        const int n = min(16, tstop - tb);
        const float (*xa)[16] = xs[w][st];

        if (n == 16) {
#pragma unroll
            for (int j = 0; j < 16; j++) {
                float n0, n1;
                if (j < 15) matvec(xa[j + 1], n0, n1);   // next-step matvec first:
                recur(m0, m1, st, j);                    // fills the tanh window
                if (j < 15) { m0 = n0; m1 = n1; }
            }
        } else {
            for (int j = 0; j < n; j++) {
                float mm0 = m0, mm1 = m1;
                if (j + 1 < n) matvec(xa[j + 1], m0, m1);
                recur(mm0, mm1, st, j);
            }
        }
        __syncwarp();

        // Reduce: lane (half, jj) sums 16 partials of step tb+jj; combine halves
        {
            const float4* pr = (const float4*)(&ps[w][st][jj][half * 16]);
            float4 a0 = pr[0], a1 = pr[1], a2 = pr[2], a3 = pr[3];
            float r0 = ((a0.x + a0.y) + (a0.z + a0.w)) + ((a1.x + a1.y) + (a1.z + a1.w));
            float r1 = ((a2.x + a2.y) + (a2.z + a2.w)) + ((a3.x + a3.y) + (a3.z + a3.w));
            float r = r0 + r1;
            r += __shfl_xor_sync(0xffffffffu, r, 16);
            int t = tb + jj;
            if (half == 0 && t >= start && t < tstop)
                out[t] = bln + r;
        }
        // no sync needed: next tile writes ps stage st^1 (double-buffered)

        if (k + 1 < nt) {
            cpawait0();
            __syncwarp();
            matvec(xs[w][st ^ 1][0], m0, m1);   // pipeline prologue of next tile
        }
        tb += 16;
    }

    // Unique last chunk writes final carries: y_h = 2z, y_hs = 0.5 + 0.5*t
    if (start + L >= B) {
        *(float2*)(out + B + 2 * lane) = make_float2(2.f * z0, 2.f * z1);
        *(float2*)(out + B + 64 + 2 * lane) =
            make_float2(fmaf(0.5f, t0s, 0.5f), fmaf(0.5f, t1s, 0.5f));
    }
}

extern "C" void kernel_launch(void* const* d_in, const int* in_sizes, int n_in,
                              void* d_out, int out_size)
{
    const float* x   = (const float*)d_in[0];
    const float* wt  = (const float*)d_in[1];
    const float* wy  = (const float*)d_in[2];
    const float* b   = (const float*)d_in[3];
    const float* wln = (const float*)d_in[4];
    const float* bln = (const float*)d_in[5];
    float* out = (float*)d_out;

    const int B = in_sizes[0] / 64;              // x is (B, T=4, I=16); row stride 64
    const int L = (B + NWARPS - 1) / NWARPS;     // steps per chunk

    rnn_scan_kernel<<<NBLOCKS, BLOCK>>>(x, wt, wy, b, wln, bln, out, B, L);
}